// round 1
// baseline (speedup 1.0000x reference)
#include <cuda_runtime.h>
#include <cuda_bf16.h>
#include <cstdint>
#include <math.h>

// Problem dims (fixed)
#define B_   4
#define L_   2048
#define D_   2048
#define R_   (B_*L_)        // 8192 rows
#define WN_  4
#define WELEM (D_*D_)       // 4194304
#define NCHUNK 16
#define CHUNK  128          // L_/NCHUNK

// ---------------- scratch (static device allocations; no cudaMalloc) ------
__device__ __nv_bfloat16 g_WQ[WN_*WELEM];        // ternary weights, bf16   (32MB)
__device__ __nv_bfloat16 g_XQ[R_*D_];            // quantized activations   (32MB)
__device__ float g_GOUT[(size_t)R_*3*D_];        // raw int sums i|f|g      (192MB)
__device__ float g_SA[R_*D_];                    // i  -> h*sigmoid(h)      (64MB)
__device__ float g_SB[R_*D_];                    // f                       (64MB)
__device__ float g_cF[B_*NCHUNK*D_];
__device__ float g_cH[B_*NCHUNK*D_];
__device__ float g_carry[B_*NCHUNK*D_];
__device__ float g_xs[R_];                       // per-row act dequant scale (1/s)
__device__ float g_os[R_];                       // per-row o dequant scale
__device__ float g_wpart[WN_*256];
__device__ float g_wmean[WN_];                   // clip(mean|W|,1e-5) == 1/ws

// ---------------- helpers ----------------
__device__ __forceinline__ float sigmoidf_(float x) { return 1.0f / (1.0f + expf(-x)); }
__device__ __forceinline__ float rsqrt_acc(float v) {
    float r = rsqrtf(v);
    r = r * (1.5f - 0.5f * v * r * r);   // one Newton step for accuracy
    return r;
}

// ---------------- weight abs-mean: deterministic two-stage reduction -------
__global__ void k_wabs_partial(const float* __restrict__ W0, const float* __restrict__ W1,
                               const float* __restrict__ W2, const float* __restrict__ W3) {
    const float* W = (blockIdx.y == 0) ? W0 : (blockIdx.y == 1) ? W1 : (blockIdx.y == 2) ? W2 : W3;
    int tid = threadIdx.x;
    size_t base = (size_t)blockIdx.x * 16384 + tid;   // 256 blocks x 16384 elems
    float s = 0.f;
    #pragma unroll 8
    for (int j = 0; j < 64; j++) s += fabsf(W[base + (size_t)j * 256]);
    __shared__ float red[256];
    red[tid] = s; __syncthreads();
    for (int st = 128; st > 0; st >>= 1) {
        if (tid < st) red[tid] += red[tid + st];
        __syncthreads();
    }
    if (tid == 0) g_wpart[blockIdx.y * 256 + blockIdx.x] = red[0];
}

__global__ void k_wfinal() {
    int w = blockIdx.x, tid = threadIdx.x;
    __shared__ float red[256];
    red[tid] = g_wpart[w * 256 + tid]; __syncthreads();
    for (int st = 128; st > 0; st >>= 1) {
        if (tid < st) red[tid] += red[tid + st];
        __syncthreads();
    }
    if (tid == 0) {
        float m = red[0] / (float)WELEM;
        g_wmean[w] = fmaxf(m, 1e-5f);   // == 1/ws (dequant factor)
    }
}

// ---------------- ternary weight quantization -----------------------------
__global__ void k_wquant(const float* __restrict__ W0, const float* __restrict__ W1,
                         const float* __restrict__ W2, const float* __restrict__ W3) {
    int i = blockIdx.x * blockDim.x + threadIdx.x;     // over WN_*WELEM/4
    int w = i >> 20;                                   // WELEM/4 = 2^20
    const float* W = (w == 0) ? W0 : (w == 1) ? W1 : (w == 2) ? W2 : W3;
    float4 v = ((const float4*)W)[i & 0xFFFFF];
    float ws = 1.0f / g_wmean[w];
    size_t o = (size_t)i * 4;
    float q0 = fminf(fmaxf(rintf(v.x * ws), -1.f), 1.f);
    float q1 = fminf(fmaxf(rintf(v.y * ws), -1.f), 1.f);
    float q2 = fminf(fmaxf(rintf(v.z * ws), -1.f), 1.f);
    float q3 = fminf(fmaxf(rintf(v.w * ws), -1.f), 1.f);
    g_WQ[o + 0] = __float2bfloat16(q0);
    g_WQ[o + 1] = __float2bfloat16(q1);
    g_WQ[o + 2] = __float2bfloat16(q2);
    g_WQ[o + 3] = __float2bfloat16(q3);
}

// ---------------- activation quantization (RMSNorm -> int8 grid) ----------
__global__ void k_actquant(const float* __restrict__ X) {
    int row = blockIdx.x, tid = threadIdx.x;
    const float* xr = X + (size_t)row * D_;
    float v[8]; float ss = 0.f;
    #pragma unroll
    for (int j = 0; j < 8; j++) { v[j] = xr[tid + j * 256]; ss += v[j] * v[j]; }
    __shared__ float red[256];
    red[tid] = ss; __syncthreads();
    for (int st = 128; st > 0; st >>= 1) {
        if (tid < st) red[tid] += red[tid + st];
        __syncthreads();
    }
    float tot = red[0];
    __syncthreads();
    float rms = rsqrt_acc(tot / (float)D_ + 1e-5f);
    float ma = 0.f;
    #pragma unroll
    for (int j = 0; j < 8; j++) { v[j] *= rms; ma = fmaxf(ma, fabsf(v[j])); }
    red[tid] = ma; __syncthreads();
    for (int st = 128; st > 0; st >>= 1) {
        if (tid < st) red[tid] = fmaxf(red[tid], red[tid + st]);
        __syncthreads();
    }
    float mx = fmaxf(red[0], 1e-5f);
    float s = 127.f / mx;
    #pragma unroll
    for (int j = 0; j < 8; j++) {
        float q = fminf(fmaxf(rintf(v[j] * s), -128.f), 127.f);
        g_XQ[(size_t)row * D_ + tid + j * 256] = __float2bfloat16(q);
    }
    if (tid == 0) g_xs[row] = mx / 127.f;
}

// ---------------- bf16 mma.sync GEMM: C[m,n] = sum_k A[m,k]*B[n,k] --------
// Tiles: BM=128, BN=128, BK=32. 256 threads = 8 warps (2m x 4n), warp 64x32.
__global__ void __launch_bounds__(256, 1) k_gemm(
    const __nv_bfloat16* __restrict__ A, const __nv_bfloat16* __restrict__ Bm,
    float* __restrict__ C, int M, int N, int K,
    const float* __restrict__ rowscale, const float* __restrict__ wscale) {

    __shared__ __nv_bfloat16 sA[128][40];
    __shared__ __nv_bfloat16 sB[128][40];

    int tid = threadIdx.x, lane = tid & 31, warp = tid >> 5;
    int wm = (warp & 1) * 64, wn = (warp >> 1) * 32;
    int g = lane >> 2, t4 = lane & 3;
    int bm = blockIdx.y * 128, bn = blockIdx.x * 128;

    float acc[4][4][4];
    #pragma unroll
    for (int a = 0; a < 4; a++)
        #pragma unroll
        for (int b = 0; b < 4; b++)
            #pragma unroll
            for (int c = 0; c < 4; c++) acc[a][b][c] = 0.f;

    for (int kt = 0; kt < K; kt += 32) {
        #pragma unroll
        for (int j = 0; j < 2; j++) {
            int r = (tid >> 2) + j * 64, c4 = tid & 3;
            *(uint4*)&sA[r][c4 * 8] = *(const uint4*)&A[(size_t)(bm + r) * K + kt + c4 * 8];
            *(uint4*)&sB[r][c4 * 8] = *(const uint4*)&Bm[(size_t)(bn + r) * K + kt + c4 * 8];
        }
        __syncthreads();
        #pragma unroll
        for (int kk = 0; kk < 32; kk += 16) {
            uint32_t af[4][4], bfr[4][2];
            #pragma unroll
            for (int mi = 0; mi < 4; mi++) {
                int r0 = wm + mi * 16 + g;
                af[mi][0] = *(const uint32_t*)&sA[r0    ][kk + t4 * 2    ];
                af[mi][1] = *(const uint32_t*)&sA[r0 + 8][kk + t4 * 2    ];
                af[mi][2] = *(const uint32_t*)&sA[r0    ][kk + t4 * 2 + 8];
                af[mi][3] = *(const uint32_t*)&sA[r0 + 8][kk + t4 * 2 + 8];
            }
            #pragma unroll
            for (int ni = 0; ni < 4; ni++) {
                int n0 = wn + ni * 8 + g;
                bfr[ni][0] = *(const uint32_t*)&sB[n0][kk + t4 * 2    ];
                bfr[ni][1] = *(const uint32_t*)&sB[n0][kk + t4 * 2 + 8];
            }
            #pragma unroll
            for (int mi = 0; mi < 4; mi++)
                #pragma unroll
                for (int ni = 0; ni < 4; ni++) {
                    asm volatile(
                        "mma.sync.aligned.m16n8k16.row.col.f32.bf16.bf16.f32 "
                        "{%0,%1,%2,%3}, {%4,%5,%6,%7}, {%8,%9}, {%0,%1,%2,%3};\n"
                        : "+f"(acc[mi][ni][0]), "+f"(acc[mi][ni][1]),
                          "+f"(acc[mi][ni][2]), "+f"(acc[mi][ni][3])
                        : "r"(af[mi][0]), "r"(af[mi][1]), "r"(af[mi][2]), "r"(af[mi][3]),
                          "r"(bfr[ni][0]), "r"(bfr[ni][1]));
                }
        }
        __syncthreads();
    }

    float wsc = rowscale ? (*wscale) : 1.f;
    #pragma unroll
    for (int mi = 0; mi < 4; mi++) {
        int r0 = bm + wm + mi * 16 + g;
        int r1 = r0 + 8;
        float s0 = rowscale ? rowscale[r0] * wsc : 1.f;
        float s1 = rowscale ? rowscale[r1] * wsc : 1.f;
        #pragma unroll
        for (int ni = 0; ni < 4; ni++) {
            int col = bn + wn + ni * 8 + t4 * 2;
            C[(size_t)r0 * N + col    ] = acc[mi][ni][0] * s0;
            C[(size_t)r0 * N + col + 1] = acc[mi][ni][1] * s0;
            C[(size_t)r1 * N + col    ] = acc[mi][ni][2] * s1;
            C[(size_t)r1 * N + col + 1] = acc[mi][ni][3] * s1;
        }
    }
}

// ---------------- i/f elementwise: dequant + sigmoid/swiglu ---------------
__global__ void k_if() {
    int idx = blockIdx.x * 256 + threadIdx.x;   // R_*D_
    int row = idx >> 11, n = idx & 2047;
    float sx = g_xs[row];
    float iv = g_GOUT[(size_t)row * 6144 + n       ] * (sx * g_wmean[0]);
    float fv = g_GOUT[(size_t)row * 6144 + 2048 + n] * (sx * g_wmean[1]);
    float f = sigmoidf_(fv);
    float i = iv * sigmoidf_(iv) * (1.f - f);
    g_SA[idx] = i;
    g_SB[idx] = f;
}

// ---------------- HGRN scan (3-pass chunked) ------------------------------
__global__ void k_scan1() {
    int idx = blockIdx.x * 256 + threadIdx.x;   // B_*NCHUNK*D_
    int d = idx & 2047, c = (idx >> 11) & 15, b = idx >> 15;
    size_t base = ((size_t)(b * L_ + c * CHUNK)) * D_ + d;
    float F = 1.f, H = 0.f;
    for (int t = 0; t < CHUNK; t++) {
        float f = g_SB[base + (size_t)t * D_];
        float iv = g_SA[base + (size_t)t * D_];
        H = f * H + iv;
        F *= f;
    }
    int o = (b * NCHUNK + c) * D_ + d;
    g_cF[o] = F; g_cH[o] = H;
}

__global__ void k_scan2() {
    int idx = blockIdx.x * 256 + threadIdx.x;   // B_*D_ = 8192
    int d = idx & 2047, b = idx >> 11;
    float carry = 0.f;
    for (int c = 0; c < NCHUNK; c++) {
        int o = (b * NCHUNK + c) * D_ + d;
        g_carry[o] = carry;
        carry = g_cF[o] * carry + g_cH[o];
    }
}

__global__ void k_scan3() {
    int idx = blockIdx.x * 256 + threadIdx.x;
    int d = idx & 2047, c = (idx >> 11) & 15, b = idx >> 15;
    size_t base = ((size_t)(b * L_ + c * CHUNK)) * D_ + d;
    float h = g_carry[(b * NCHUNK + c) * D_ + d];
    for (int t = 0; t < CHUNK; t++) {
        float f = g_SB[base + (size_t)t * D_];
        float iv = g_SA[base + (size_t)t * D_];
        h = f * h + iv;
        g_SA[base + (size_t)t * D_] = h * sigmoidf_(h);   // overwrite i with h*sig(h)
    }
}

// ---------------- o = rmsnorm(g)*w*(h*sig(h)), then re-quantize o ----------
__global__ void k_og(const float* __restrict__ gnw) {
    int row = blockIdx.x, tid = threadIdx.x;
    float sg = g_xs[row] * g_wmean[2];
    float gv[8]; float ss = 0.f;
    #pragma unroll
    for (int j = 0; j < 8; j++) {
        gv[j] = g_GOUT[(size_t)row * 6144 + 4096 + tid + j * 256] * sg;
        ss += gv[j] * gv[j];
    }
    __shared__ float red[256];
    red[tid] = ss; __syncthreads();
    for (int st = 128; st > 0; st >>= 1) {
        if (tid < st) red[tid] += red[tid + st];
        __syncthreads();
    }
    float tot = red[0];
    __syncthreads();
    float rg = rsqrt_acc(tot / (float)D_ + 1e-5f);

    float ov[8]; ss = 0.f;
    #pragma unroll
    for (int j = 0; j < 8; j++) {
        float hs = g_SA[(size_t)row * D_ + tid + j * 256];
        ov[j] = gv[j] * rg * gnw[tid + j * 256] * hs;
        ss += ov[j] * ov[j];
    }
    red[tid] = ss; __syncthreads();
    for (int st = 128; st > 0; st >>= 1) {
        if (tid < st) red[tid] += red[tid + st];
        __syncthreads();
    }
    float tot2 = red[0];
    __syncthreads();
    float ro = rsqrt_acc(tot2 / (float)D_ + 1e-5f);

    float ma = 0.f;
    #pragma unroll
    for (int j = 0; j < 8; j++) { ov[j] *= ro; ma = fmaxf(ma, fabsf(ov[j])); }
    red[tid] = ma; __syncthreads();
    for (int st = 128; st > 0; st >>= 1) {
        if (tid < st) red[tid] = fmaxf(red[tid], red[tid + st]);
        __syncthreads();
    }
    float mx = fmaxf(red[0], 1e-5f);
    float s = 127.f / mx;
    #pragma unroll
    for (int j = 0; j < 8; j++) {
        float q = fminf(fmaxf(rintf(ov[j] * s), -128.f), 127.f);
        g_XQ[(size_t)row * D_ + tid + j * 256] = __float2bfloat16(q);
    }
    if (tid == 0) g_os[row] = mx / 127.f;
}

// ---------------- launch ---------------------------------------------------
extern "C" void kernel_launch(void* const* d_in, const int* in_sizes, int n_in,
                              void* d_out, int out_size) {
    const float* X   = (const float*)d_in[0];
    const float* Wi  = (const float*)d_in[1];
    const float* Wf  = (const float*)d_in[2];
    const float* Wg  = (const float*)d_in[3];
    const float* Wo  = (const float*)d_in[4];
    const float* gnw = (const float*)d_in[5];
    float* out = (float*)d_out;

    void *pWQ = nullptr, *pXQ = nullptr, *pGOUT = nullptr, *pOS = nullptr, *pWM = nullptr;
    cudaGetSymbolAddress(&pWQ, g_WQ);
    cudaGetSymbolAddress(&pXQ, g_XQ);
    cudaGetSymbolAddress(&pGOUT, g_GOUT);
    cudaGetSymbolAddress(&pOS, g_os);
    cudaGetSymbolAddress(&pWM, g_wmean);

    // 1. weight scales (deterministic)
    k_wabs_partial<<<dim3(256, 4), 256>>>(Wi, Wf, Wg, Wo);
    k_wfinal<<<4, 256>>>();
    // 2. quantize weights (ternary, bf16)
    k_wquant<<<16384, 256>>>(Wi, Wf, Wg, Wo);
    // 3. quantize activations
    k_actquant<<<R_, 256>>>(X);
    // 4. fused GEMM for i|f|g raw integer sums: [8192 x 6144 x 2048]
    k_gemm<<<dim3(6144 / 128, R_ / 128), 256>>>(
        (const __nv_bfloat16*)pXQ, (const __nv_bfloat16*)pWQ, (float*)pGOUT,
        R_, 3 * D_, D_, nullptr, nullptr);
    // 5. i/f elementwise
    k_if<<<(R_ * D_) / 256, 256>>>();
    // 6. HGRN scan
    k_scan1<<<(B_ * NCHUNK * D_) / 256, 256>>>();
    k_scan2<<<(B_ * D_) / 256, 256>>>();
    k_scan3<<<(B_ * NCHUNK * D_) / 256, 256>>>();
    // 7. output gate + o quantization
    k_og<<<R_, 256>>>(gnw);
    // 8. final GEMM with dequant epilogue -> d_out
    k_gemm<<<dim3(D_ / 128, R_ / 128), 256>>>(
        (const __nv_bfloat16*)pXQ, (const __nv_bfloat16*)pWQ + (size_t)3 * WELEM, out,
        R_, D_, D_, (const float*)pOS, (const float*)pWM + 3);
}